// round 3
// baseline (speedup 1.0000x reference)
#include <cuda_runtime.h>
#include <cuda_bf16.h>
#include <math_constants.h>

#define DIM 4096
#define CAP 8192
#define VEC (DIM / 4)          // 1024 float4 per row
#define ITER (VEC / 32)        // 32 float4 per lane per row
#define MAXK 64

// Scratch (no allocations allowed)
__device__ float g_scores[CAP];
__device__ float g_retrieved[DIM];

// ---------------------------------------------------------------------------
// Kernel 1: weighted cosine-similarity scores.
// Warp-per-2-rows: no block barriers, q loaded once per 2 rows.
// grid = CAP / 16 = 512 blocks x 256 threads (8 warps, 2 rows each).
// ---------------------------------------------------------------------------
__global__ void __launch_bounds__(256)
scores_kernel(const float* __restrict__ query,
              const float* __restrict__ memory_bank,
              const float* __restrict__ importance,
              const float* __restrict__ age) {
    int warp = (blockIdx.x << 3) + (threadIdx.x >> 5);
    int lane = threadIdx.x & 31;
    int row0 = warp * 2;
    int row1 = row0 + 1;

    const float4* q4 = reinterpret_cast<const float4*>(query);
    const float4* m0 = reinterpret_cast<const float4*>(memory_bank + (size_t)row0 * DIM);
    const float4* m1 = reinterpret_cast<const float4*>(memory_bank + (size_t)row1 * DIM);

    float dot0 = 0.f, dot1 = 0.f, ms0 = 0.f, ms1 = 0.f, qsq = 0.f;
    #pragma unroll 4
    for (int i = 0; i < ITER; i++) {
        int idx = lane + (i << 5);
        float4 q = q4[idx];
        float4 a = m0[idx];
        float4 b = m1[idx];
        dot0 += q.x * a.x + q.y * a.y + q.z * a.z + q.w * a.w;
        ms0  += a.x * a.x + a.y * a.y + a.z * a.z + a.w * a.w;
        dot1 += q.x * b.x + q.y * b.y + q.z * b.z + q.w * b.w;
        ms1  += b.x * b.x + b.y * b.y + b.z * b.z + b.w * b.w;
        qsq  += q.x * q.x + q.y * q.y + q.z * q.z + q.w * q.w;
    }
    #pragma unroll
    for (int off = 16; off > 0; off >>= 1) {
        dot0 += __shfl_xor_sync(0xffffffffu, dot0, off);
        dot1 += __shfl_xor_sync(0xffffffffu, dot1, off);
        ms0  += __shfl_xor_sync(0xffffffffu, ms0,  off);
        ms1  += __shfl_xor_sync(0xffffffffu, ms1,  off);
        qsq  += __shfl_xor_sync(0xffffffffu, qsq,  off);
    }
    if (lane == 0) {
        float qn = sqrtf(qsq);
        float s0 = dot0 / fmaxf(qn * sqrtf(ms0), 1e-8f);
        float s1 = dot1 / fmaxf(qn * sqrtf(ms1), 1e-8f);
        g_scores[row0] = s0 * importance[row0] * expf(-0.001f * age[row0]);
        g_scores[row1] = s1 * importance[row1] * expf(-0.001f * age[row1]);
    }
}

// ---------------------------------------------------------------------------
// Kernel 2: top-k + mean pool. Single block, single-pass selection.
// Fast path (k <= 8): each thread keeps a sorted top-8 list in registers
// from a single scan of its 32 scores, then an 8-level tree merge in smem.
// Tie-break matches jax.lax.top_k: on equal value, smaller index wins.
// ---------------------------------------------------------------------------
__device__ __forceinline__ bool cmp_gt(float av, int ai, float bv, int bi) {
    return (av > bv) || (av == bv && ai < bi);
}

__global__ void __launch_bounds__(256, 1)
topk_mean_kernel(const float* __restrict__ memory_bank,
                 const int* __restrict__ top_k_ptr) {
    __shared__ float s[CAP];                         // 32 KB, aliased below
    __shared__ int   chosen[MAXK];
    __shared__ float rv[256];
    __shared__ int   ri[256];

    int tid = threadIdx.x;
    int k = top_k_ptr[0];
    if (k < 1) k = 1;
    if (k > MAXK) k = MAXK;

    if (k <= 8) {
        // -------- fast path: single-pass per-thread top-8 --------
        float lv[8]; int li[8];
        #pragma unroll
        for (int j = 0; j < 8; j++) { lv[j] = -CUDART_INF_F; li[j] = CAP + j; }

        // each thread scans 32 scores (ascending index preserves tie order)
        #pragma unroll 4
        for (int t = 0; t < CAP / 256; t++) {
            int i = tid + (t << 8);
            float v = g_scores[i];
            if (cmp_gt(v, i, lv[7], li[7])) {
                lv[7] = v; li[7] = i;
                #pragma unroll
                for (int j = 7; j > 0; j--) {
                    if (cmp_gt(lv[j], li[j], lv[j-1], li[j-1])) {
                        float tv = lv[j]; lv[j] = lv[j-1]; lv[j-1] = tv;
                        int   ti = li[j]; li[j] = li[j-1]; li[j-1] = ti;
                    }
                }
            }
        }

        // alias smem: 256 lists of 8 (val 8KB + idx 8KB) inside s[]
        float (*sv)[8] = reinterpret_cast<float(*)[8]>(s);
        int   (*si)[8] = reinterpret_cast<int(*)[8]>(s + 2048);
        #pragma unroll
        for (int j = 0; j < 8; j++) { sv[tid][j] = lv[j]; si[tid][j] = li[j]; }

        // tree merge: 256 -> 1 sorted top-8 lists
        for (int stride = 128; stride >= 1; stride >>= 1) {
            __syncthreads();
            if (tid < stride) {
                float av[8], bv[8], mv[8];
                int   ai[8], bi[8], mi[8];
                #pragma unroll
                for (int j = 0; j < 8; j++) {
                    av[j] = sv[tid][j];          ai[j] = si[tid][j];
                    bv[j] = sv[tid + stride][j]; bi[j] = si[tid + stride][j];
                }
                int pa = 0, pb = 0;
                #pragma unroll
                for (int j = 0; j < 8; j++) {
                    if (cmp_gt(av[pa], ai[pa], bv[pb], bi[pb])) {
                        mv[j] = av[pa]; mi[j] = ai[pa]; pa++;
                    } else {
                        mv[j] = bv[pb]; mi[j] = bi[pb]; pb++;
                    }
                }
                #pragma unroll
                for (int j = 0; j < 8; j++) { sv[tid][j] = mv[j]; si[tid][j] = mi[j]; }
            }
        }
        __syncthreads();
        if (tid < k) chosen[tid] = si[0][tid];
        __syncthreads();
    } else {
        // -------- fallback: iterative argmax rounds --------
        for (int i = tid; i < CAP; i += 256) s[i] = g_scores[i];
        __syncthreads();
        for (int r = 0; r < k; r++) {
            float best = -CUDART_INF_F; int bi = CAP;
            for (int i = tid; i < CAP; i += 256) {
                float v = s[i];
                if (v > best) { best = v; bi = i; }
            }
            rv[tid] = best; ri[tid] = bi;
            __syncthreads();
            for (int off = 128; off > 0; off >>= 1) {
                if (tid < off) {
                    float ov = rv[tid + off]; int oi = ri[tid + off];
                    if (ov > rv[tid] || (ov == rv[tid] && oi < ri[tid])) {
                        rv[tid] = ov; ri[tid] = oi;
                    }
                }
                __syncthreads();
            }
            if (tid == 0) { chosen[r] = ri[0]; s[ri[0]] = -CUDART_INF_F; }
            __syncthreads();
        }
    }

    // mean-pool the k selected rows -> g_retrieved
    float invk = 1.0f / (float)k;
    for (int j = tid; j < VEC; j += 256) {
        float4 acc = make_float4(0.f, 0.f, 0.f, 0.f);
        for (int r = 0; r < k; r++) {
            const float4* row4 =
                reinterpret_cast<const float4*>(memory_bank + (size_t)chosen[r] * DIM);
            float4 v = row4[j];
            acc.x += v.x; acc.y += v.y; acc.z += v.z; acc.w += v.w;
        }
        reinterpret_cast<float4*>(g_retrieved)[j] =
            make_float4(acc.x * invk, acc.y * invk, acc.z * invk, acc.w * invk);
    }
}

// ---------------------------------------------------------------------------
// Kernel 3: out = W_dec @ retrieved + b_dec.  Warp-per-2-rows.
// grid = DIM / 16 = 256 blocks x 256 threads.
// ---------------------------------------------------------------------------
__global__ void __launch_bounds__(256)
decode_kernel(const float* __restrict__ W_dec,
              const float* __restrict__ b_dec,
              float* __restrict__ out) {
    int warp = (blockIdx.x << 3) + (threadIdx.x >> 5);
    int lane = threadIdx.x & 31;
    int row0 = warp * 2;
    int row1 = row0 + 1;

    const float4* r4 = reinterpret_cast<const float4*>(g_retrieved);
    const float4* w0 = reinterpret_cast<const float4*>(W_dec + (size_t)row0 * DIM);
    const float4* w1 = reinterpret_cast<const float4*>(W_dec + (size_t)row1 * DIM);

    float a0 = 0.f, a1 = 0.f;
    #pragma unroll 4
    for (int i = 0; i < ITER; i++) {
        int idx = lane + (i << 5);
        float4 r = r4[idx];
        float4 x = w0[idx];
        float4 y = w1[idx];
        a0 += r.x * x.x + r.y * x.y + r.z * x.z + r.w * x.w;
        a1 += r.x * y.x + r.y * y.y + r.z * y.z + r.w * y.w;
    }
    #pragma unroll
    for (int off = 16; off > 0; off >>= 1) {
        a0 += __shfl_xor_sync(0xffffffffu, a0, off);
        a1 += __shfl_xor_sync(0xffffffffu, a1, off);
    }
    if (lane == 0) {
        out[row0] = a0 + b_dec[row0];
        out[row1] = a1 + b_dec[row1];
    }
}

// ---------------------------------------------------------------------------
extern "C" void kernel_launch(void* const* d_in, const int* in_sizes, int n_in,
                              void* d_out, int out_size) {
    const float* query       = (const float*)d_in[0];
    const float* memory_bank = (const float*)d_in[1];
    const float* importance  = (const float*)d_in[2];
    const float* age         = (const float*)d_in[3];
    const float* W_dec       = (const float*)d_in[4];
    const float* b_dec       = (const float*)d_in[5];
    const int*   top_k       = (const int*)d_in[6];
    float* out = (float*)d_out;

    scores_kernel<<<CAP / 16, 256>>>(query, memory_bank, importance, age);
    topk_mean_kernel<<<1, 256>>>(memory_bank, top_k);
    decode_kernel<<<DIM / 16, 256>>>(W_dec, b_dec, out);
}

// round 4
// speedup vs baseline: 1.1591x; 1.1591x over previous
#include <cuda_runtime.h>
#include <cuda_bf16.h>
#include <math_constants.h>

#define DIM 4096
#define CAP 8192
#define VEC (DIM / 4)      // 1024 float4 per row
#define MAXK 64

// Scratch (no allocations allowed)
__device__ float g_scores[CAP];
__device__ float g_retrieved[DIM];

// ---------------------------------------------------------------------------
// Block-wide 3-value sum reduction helper (warp shuffle + smem)
// ---------------------------------------------------------------------------
__device__ __forceinline__ void block_reduce3(float& a, float& b, float& c) {
    __shared__ float sa[8], sb[8], sc[8];
    int lane = threadIdx.x & 31;
    int wid  = threadIdx.x >> 5;
    #pragma unroll
    for (int off = 16; off > 0; off >>= 1) {
        a += __shfl_down_sync(0xffffffffu, a, off);
        b += __shfl_down_sync(0xffffffffu, b, off);
        c += __shfl_down_sync(0xffffffffu, c, off);
    }
    if (lane == 0) { sa[wid] = a; sb[wid] = b; sc[wid] = c; }
    __syncthreads();
    if (wid == 0) {
        int nw = blockDim.x >> 5;
        a = (lane < nw) ? sa[lane] : 0.0f;
        b = (lane < nw) ? sb[lane] : 0.0f;
        c = (lane < nw) ? sc[lane] : 0.0f;
        #pragma unroll
        for (int off = 4; off > 0; off >>= 1) {
            a += __shfl_down_sync(0xffffffffu, a, off);
            b += __shfl_down_sync(0xffffffffu, b, off);
            c += __shfl_down_sync(0xffffffffu, c, off);
        }
    }
}

// ---------------------------------------------------------------------------
// Kernel 1: weighted cosine-similarity scores. One block per memory row.
// memory_bank is touched once -> __ldcs (streaming); query stays L1-resident
// across the ~55 sequential blocks per SM.
// ---------------------------------------------------------------------------
__global__ void __launch_bounds__(256, 8)
scores_kernel(const float* __restrict__ query,
              const float* __restrict__ memory_bank,
              const float* __restrict__ importance,
              const float* __restrict__ age) {
    int row = blockIdx.x;
    const float4* q4 = reinterpret_cast<const float4*>(query);
    const float4* m4 = reinterpret_cast<const float4*>(memory_bank + (size_t)row * DIM);

    float dot = 0.0f, msq = 0.0f, qsq = 0.0f;
    #pragma unroll
    for (int i = 0; i < VEC / 256; i++) {
        int idx = threadIdx.x + (i << 8);
        float4 m = __ldcs(m4 + idx);
        float4 q = q4[idx];
        dot += q.x * m.x + q.y * m.y + q.z * m.z + q.w * m.w;
        msq += m.x * m.x + m.y * m.y + m.z * m.z + m.w * m.w;
        qsq += q.x * q.x + q.y * q.y + q.z * q.z + q.w * q.w;
    }
    block_reduce3(dot, msq, qsq);
    if (threadIdx.x == 0) {
        float denom = fmaxf(sqrtf(qsq) * sqrtf(msq), 1e-8f);
        float sim = dot / denom;
        g_scores[row] = sim * importance[row] * expf(-0.001f * age[row]);
    }
}

// ---------------------------------------------------------------------------
// Kernel 2: top-k + mean pool. Single block, single-pass selection.
// Fast path (k <= 8): per-thread sorted top-8 in registers from one scan,
// then an 8-level tree merge in smem. Tie-break matches jax.lax.top_k
// (smaller index wins on equal value).
// ---------------------------------------------------------------------------
__device__ __forceinline__ bool cmp_gt(float av, int ai, float bv, int bi) {
    return (av > bv) || (av == bv && ai < bi);
}

__global__ void __launch_bounds__(256, 1)
topk_mean_kernel(const float* __restrict__ memory_bank,
                 const int* __restrict__ top_k_ptr) {
    __shared__ float s[CAP];                         // 32 KB, aliased below
    __shared__ int   chosen[MAXK];
    __shared__ float rv[256];
    __shared__ int   ri[256];

    int tid = threadIdx.x;
    int k = top_k_ptr[0];
    if (k < 1) k = 1;
    if (k > MAXK) k = MAXK;

    if (k <= 8) {
        // -------- fast path: single-pass per-thread top-8 --------
        float lv[8]; int li[8];
        #pragma unroll
        for (int j = 0; j < 8; j++) { lv[j] = -CUDART_INF_F; li[j] = CAP + j; }

        #pragma unroll 4
        for (int t = 0; t < CAP / 256; t++) {
            int i = tid + (t << 8);
            float v = g_scores[i];
            if (cmp_gt(v, i, lv[7], li[7])) {
                lv[7] = v; li[7] = i;
                #pragma unroll
                for (int j = 7; j > 0; j--) {
                    if (cmp_gt(lv[j], li[j], lv[j-1], li[j-1])) {
                        float tv = lv[j]; lv[j] = lv[j-1]; lv[j-1] = tv;
                        int   ti = li[j]; li[j] = li[j-1]; li[j-1] = ti;
                    }
                }
            }
        }

        // alias smem: 256 lists of 8 (val 8KB + idx 8KB) inside s[]
        float (*sv)[8] = reinterpret_cast<float(*)[8]>(s);
        int   (*si)[8] = reinterpret_cast<int(*)[8]>(s + 2048);
        #pragma unroll
        for (int j = 0; j < 8; j++) { sv[tid][j] = lv[j]; si[tid][j] = li[j]; }

        // tree merge: 256 -> 1 sorted top-8 lists
        for (int stride = 128; stride >= 1; stride >>= 1) {
            __syncthreads();
            if (tid < stride) {
                float av[8], bv[8], mv[8];
                int   ai[8], bi[8], mi[8];
                #pragma unroll
                for (int j = 0; j < 8; j++) {
                    av[j] = sv[tid][j];          ai[j] = si[tid][j];
                    bv[j] = sv[tid + stride][j]; bi[j] = si[tid + stride][j];
                }
                int pa = 0, pb = 0;
                #pragma unroll
                for (int j = 0; j < 8; j++) {
                    if (cmp_gt(av[pa], ai[pa], bv[pb], bi[pb])) {
                        mv[j] = av[pa]; mi[j] = ai[pa]; pa++;
                    } else {
                        mv[j] = bv[pb]; mi[j] = bi[pb]; pb++;
                    }
                }
                #pragma unroll
                for (int j = 0; j < 8; j++) { sv[tid][j] = mv[j]; si[tid][j] = mi[j]; }
            }
        }
        __syncthreads();
        if (tid < k) chosen[tid] = si[0][tid];
        __syncthreads();
    } else {
        // -------- fallback: iterative argmax rounds --------
        for (int i = tid; i < CAP; i += 256) s[i] = g_scores[i];
        __syncthreads();
        for (int r = 0; r < k; r++) {
            float best = -CUDART_INF_F; int bi = CAP;
            for (int i = tid; i < CAP; i += 256) {
                float v = s[i];
                if (v > best) { best = v; bi = i; }
            }
            rv[tid] = best; ri[tid] = bi;
            __syncthreads();
            for (int off = 128; off > 0; off >>= 1) {
                if (tid < off) {
                    float ov = rv[tid + off]; int oi = ri[tid + off];
                    if (ov > rv[tid] || (ov == rv[tid] && oi < ri[tid])) {
                        rv[tid] = ov; ri[tid] = oi;
                    }
                }
                __syncthreads();
            }
            if (tid == 0) { chosen[r] = ri[0]; s[ri[0]] = -CUDART_INF_F; }
            __syncthreads();
        }
    }

    // mean-pool the k selected rows -> g_retrieved
    float invk = 1.0f / (float)k;
    for (int j = tid; j < VEC; j += 256) {
        float4 acc = make_float4(0.f, 0.f, 0.f, 0.f);
        for (int r = 0; r < k; r++) {
            const float4* row4 =
                reinterpret_cast<const float4*>(memory_bank + (size_t)chosen[r] * DIM);
            float4 v = row4[j];
            acc.x += v.x; acc.y += v.y; acc.z += v.z; acc.w += v.w;
        }
        reinterpret_cast<float4*>(g_retrieved)[j] =
            make_float4(acc.x * invk, acc.y * invk, acc.z * invk, acc.w * invk);
    }
}

// ---------------------------------------------------------------------------
// Kernel 3: out[i] = b[i] + sum_j W[i][j] * retrieved[j]. One block per out
// element. W_dec streamed (__ldcs); retrieved stays L1-resident.
// ---------------------------------------------------------------------------
__global__ void __launch_bounds__(256, 8)
decode_kernel(const float* __restrict__ W_dec,
              const float* __restrict__ b_dec,
              float* __restrict__ out) {
    int row = blockIdx.x;
    const float4* w4 = reinterpret_cast<const float4*>(W_dec + (size_t)row * DIM);
    const float4* r4 = reinterpret_cast<const float4*>(g_retrieved);

    float acc = 0.0f, d1 = 0.0f, d2 = 0.0f;
    #pragma unroll
    for (int i = 0; i < VEC / 256; i++) {
        int idx = threadIdx.x + (i << 8);
        float4 w = __ldcs(w4 + idx);
        float4 r = r4[idx];
        acc += w.x * r.x + w.y * r.y + w.z * r.z + w.w * r.w;
    }
    block_reduce3(acc, d1, d2);
    if (threadIdx.x == 0) out[row] = acc + b_dec[row];
}

// ---------------------------------------------------------------------------
extern "C" void kernel_launch(void* const* d_in, const int* in_sizes, int n_in,
                              void* d_out, int out_size) {
    const float* query       = (const float*)d_in[0];
    const float* memory_bank = (const float*)d_in[1];
    const float* importance  = (const float*)d_in[2];
    const float* age         = (const float*)d_in[3];
    const float* W_dec       = (const float*)d_in[4];
    const float* b_dec       = (const float*)d_in[5];
    const int*   top_k       = (const int*)d_in[6];
    float* out = (float*)d_out;

    scores_kernel<<<CAP, 256>>>(query, memory_bank, importance, age);
    topk_mean_kernel<<<1, 256>>>(memory_bank, top_k);
    decode_kernel<<<DIM, 256>>>(W_dec, b_dec, out);
}

// round 7
// speedup vs baseline: 1.3692x; 1.1813x over previous
#include <cuda_runtime.h>
#include <cuda_bf16.h>
#include <math_constants.h>

#define DIM 4096
#define CAP 8192
#define VEC (DIM / 4)      // 1024 float4 per row
#define MAXK 64

// Scratch (no allocations allowed)
__device__ float g_scores[CAP];
__device__ float g_retrieved[DIM];

// ---------------------------------------------------------------------------
// Block-wide 3-value sum reduction helper (warp shuffle + smem)
// ---------------------------------------------------------------------------
__device__ __forceinline__ void block_reduce3(float& a, float& b, float& c) {
    __shared__ float sa[8], sb[8], sc[8];
    int lane = threadIdx.x & 31;
    int wid  = threadIdx.x >> 5;
    #pragma unroll
    for (int off = 16; off > 0; off >>= 1) {
        a += __shfl_down_sync(0xffffffffu, a, off);
        b += __shfl_down_sync(0xffffffffu, b, off);
        c += __shfl_down_sync(0xffffffffu, c, off);
    }
    if (lane == 0) { sa[wid] = a; sb[wid] = b; sc[wid] = c; }
    __syncthreads();
    if (wid == 0) {
        int nw = blockDim.x >> 5;
        a = (lane < nw) ? sa[lane] : 0.0f;
        b = (lane < nw) ? sb[lane] : 0.0f;
        c = (lane < nw) ? sc[lane] : 0.0f;
        #pragma unroll
        for (int off = 4; off > 0; off >>= 1) {
            a += __shfl_down_sync(0xffffffffu, a, off);
            b += __shfl_down_sync(0xffffffffu, b, off);
            c += __shfl_down_sync(0xffffffffu, c, off);
        }
    }
}

// ---------------------------------------------------------------------------
// Kernel 1: weighted cosine-similarity scores. One block per memory row.
// (proven R4 version: 26.8us, DRAM 64.9%)
// ---------------------------------------------------------------------------
__global__ void __launch_bounds__(256, 8)
scores_kernel(const float* __restrict__ query,
              const float* __restrict__ memory_bank,
              const float* __restrict__ importance,
              const float* __restrict__ age) {
    int row = blockIdx.x;
    const float4* q4 = reinterpret_cast<const float4*>(query);
    const float4* m4 = reinterpret_cast<const float4*>(memory_bank + (size_t)row * DIM);

    float dot = 0.0f, msq = 0.0f, qsq = 0.0f;
    #pragma unroll
    for (int i = 0; i < VEC / 256; i++) {
        int idx = threadIdx.x + (i << 8);
        float4 m = __ldcs(m4 + idx);
        float4 q = q4[idx];
        dot += q.x * m.x + q.y * m.y + q.z * m.z + q.w * m.w;
        msq += m.x * m.x + m.y * m.y + m.z * m.z + m.w * m.w;
        qsq += q.x * q.x + q.y * q.y + q.z * q.z + q.w * q.w;
    }
    block_reduce3(dot, msq, qsq);
    if (threadIdx.x == 0) {
        float denom = fmaxf(sqrtf(qsq) * sqrtf(msq), 1e-8f);
        float sim = dot / denom;
        g_scores[row] = sim * importance[row] * expf(-0.001f * age[row]);
    }
}

// ---------------------------------------------------------------------------
// Kernel 2: top-k + mean pool. Single block.
// All __syncthreads() are executed UNCONDITIONALLY by all 256 threads
// (R5 hung on barriers inside divergent branches).
// Tie-break matches jax.lax.top_k (smaller index wins on equal value).
// ---------------------------------------------------------------------------
__device__ __forceinline__ bool cmp_gt(float av, int ai, float bv, int bi) {
    return (av > bv) || (av == bv && ai < bi);
}

__global__ void __launch_bounds__(256, 1)
topk_mean_kernel(const float* __restrict__ memory_bank,
                 const int* __restrict__ top_k_ptr) {
    __shared__ float s[CAP];                         // 32 KB staged scores
    __shared__ int   chosen[MAXK];
    __shared__ float rv[256];
    __shared__ int   ri[256];

    int tid = threadIdx.x;

    // stage: independent loads -> full MLP
    #pragma unroll
    for (int t = 0; t < CAP / 256; t++) {
        int i = tid + (t << 8);
        s[i] = g_scores[i];
    }
    __syncthreads();

    int k = top_k_ptr[0];
    if (k < 1) k = 1;
    if (k > MAXK) k = MAXK;

    if (k <= 8) {
        // -------- per-thread sorted top-8 from SMEM --------
        float lv[8]; int li[8];
        #pragma unroll
        for (int j = 0; j < 8; j++) { lv[j] = -CUDART_INF_F; li[j] = CAP + j; }

        #pragma unroll 4
        for (int t = 0; t < CAP / 256; t++) {
            int i = tid + (t << 8);          // ascending index order
            float v = s[i];
            if (cmp_gt(v, i, lv[7], li[7])) {
                lv[7] = v; li[7] = i;
                #pragma unroll
                for (int j = 7; j > 0; j--) {
                    if (cmp_gt(lv[j], li[j], lv[j-1], li[j-1])) {
                        float tv = lv[j]; lv[j] = lv[j-1]; lv[j-1] = tv;
                        int   ti = li[j]; li[j] = li[j-1]; li[j-1] = ti;
                    }
                }
            }
        }
        __syncthreads();   // ALL threads: done reading s; safe to alias

        // alias smem: 256 sorted lists of 8 (val 8KB + idx 8KB)
        float (*sv)[8] = reinterpret_cast<float(*)[8]>(s);
        int   (*si)[8] = reinterpret_cast<int(*)[8]>(s + 2048);
        #pragma unroll
        for (int j = 0; j < 8; j++) { sv[tid][j] = lv[j]; si[tid][j] = li[j]; }
        __syncthreads();

        // tree merge 256 -> 1. Barriers hoisted out of the guarded work:
        // every thread executes exactly the same __syncthreads() sequence.
        for (int stride = 128; stride >= 1; stride >>= 1) {
            bool active = (tid < stride);
            float mv[8]; int mi[8];
            if (active) {
                int pa = 0, pb = 0;
                #pragma unroll
                for (int j = 0; j < 8; j++) {
                    float av = sv[tid][pa];          int ai = si[tid][pa];
                    float bv = sv[tid + stride][pb]; int bi = si[tid + stride][pb];
                    if (cmp_gt(av, ai, bv, bi)) { mv[j] = av; mi[j] = ai; pa++; }
                    else                        { mv[j] = bv; mi[j] = bi; pb++; }
                }
            }
            __syncthreads();       // all threads
            if (active) {
                #pragma unroll
                for (int j = 0; j < 8; j++) { sv[tid][j] = mv[j]; si[tid][j] = mi[j]; }
            }
            __syncthreads();       // all threads
        }
        if (tid < k) chosen[tid] = si[0][tid];
        __syncthreads();
    } else {
        // -------- fallback: iterative argmax rounds over staged smem --------
        for (int r = 0; r < k; r++) {
            float best = -CUDART_INF_F; int bi = CAP;
            for (int i = tid; i < CAP; i += 256) {
                float v = s[i];
                if (v > best) { best = v; bi = i; }
            }
            rv[tid] = best; ri[tid] = bi;
            __syncthreads();
            for (int off = 128; off > 0; off >>= 1) {
                if (tid < off) {
                    float ov = rv[tid + off]; int oi = ri[tid + off];
                    if (ov > rv[tid] || (ov == rv[tid] && oi < ri[tid])) {
                        rv[tid] = ov; ri[tid] = oi;
                    }
                }
                __syncthreads();
            }
            if (tid == 0) { chosen[r] = ri[0]; s[ri[0]] = -CUDART_INF_F; }
            __syncthreads();
        }
    }

    // mean-pool the k selected rows -> g_retrieved (independent loads, MLP=k)
    float invk = 1.0f / (float)k;
    for (int j = tid; j < VEC; j += 256) {
        float4 acc = make_float4(0.f, 0.f, 0.f, 0.f);
        for (int r = 0; r < k; r++) {
            const float4* row4 =
                reinterpret_cast<const float4*>(memory_bank + (size_t)chosen[r] * DIM);
            float4 v = row4[j];
            acc.x += v.x; acc.y += v.y; acc.z += v.z; acc.w += v.w;
        }
        reinterpret_cast<float4*>(g_retrieved)[j] =
            make_float4(acc.x * invk, acc.y * invk, acc.z * invk, acc.w * invk);
    }
}

// ---------------------------------------------------------------------------
// Kernel 3: out = W_dec @ retrieved + b_dec. One block per TWO rows
// (grid 2048: epilogue amortized 2x, still ~13 blocks/SM).
// ---------------------------------------------------------------------------
__global__ void __launch_bounds__(256)
decode_kernel(const float* __restrict__ W_dec,
              const float* __restrict__ b_dec,
              float* __restrict__ out) {
    int row0 = blockIdx.x * 2;
    int row1 = row0 + 1;
    const float4* w0 = reinterpret_cast<const float4*>(W_dec + (size_t)row0 * DIM);
    const float4* w1 = reinterpret_cast<const float4*>(W_dec + (size_t)row1 * DIM);
    const float4* r4 = reinterpret_cast<const float4*>(g_retrieved);

    float a0 = 0.0f, a1 = 0.0f, dz = 0.0f;
    #pragma unroll
    for (int i = 0; i < VEC / 256; i++) {
        int idx = threadIdx.x + (i << 8);
        float4 x = __ldcs(w0 + idx);
        float4 y = __ldcs(w1 + idx);
        float4 r = r4[idx];
        a0 += r.x * x.x + r.y * x.y + r.z * x.z + r.w * x.w;
        a1 += r.x * y.x + r.y * y.y + r.z * y.z + r.w * y.w;
    }
    block_reduce3(a0, a1, dz);
    if (threadIdx.x == 0) {
        out[row0] = a0 + b_dec[row0];
        out[row1] = a1 + b_dec[row1];
    }
}

// ---------------------------------------------------------------------------
extern "C" void kernel_launch(void* const* d_in, const int* in_sizes, int n_in,
                              void* d_out, int out_size) {
    const float* query       = (const float*)d_in[0];
    const float* memory_bank = (const float*)d_in[1];
    const float* importance  = (const float*)d_in[2];
    const float* age         = (const float*)d_in[3];
    const float* W_dec       = (const float*)d_in[4];
    const float* b_dec       = (const float*)d_in[5];
    const int*   top_k       = (const int*)d_in[6];
    float* out = (float*)d_out;

    scores_kernel<<<CAP, 256>>>(query, memory_bank, importance, age);
    topk_mean_kernel<<<1, 256>>>(memory_bank, top_k);
    decode_kernel<<<DIM / 2, 256>>>(W_dec, b_dec, out);
}